// round 7
// baseline (speedup 1.0000x reference)
#include <cuda_runtime.h>
#include <cuda_bf16.h>
#include <cstdint>
#include <stdint.h>
#include <math.h>

#define NTOK   4096      // B*S
#define HID    2048
#define NH     16
#define HD     128
#define MLPD   8192
#define SEQL   2048

// ------------------------- persistent device scratch -------------------------
__device__ __nv_bfloat16 g_wq[HID * HID];
__device__ __nv_bfloat16 g_wk[HID * HID];
__device__ __nv_bfloat16 g_wv[HID * HID];
__device__ __nv_bfloat16 g_wo[HID * HID];
__device__ __nv_bfloat16 g_wg[MLPD * HID];
__device__ __nv_bfloat16 g_wu[MLPD * HID];
__device__ __nv_bfloat16 g_wd[HID * MLPD];
__device__ float g_sq[HID], g_sk[HID], g_sv[HID], g_so[HID];
__device__ float g_sg[MLPD], g_su[MLPD], g_sd[HID];

__device__ __nv_bfloat16 g_aq[NTOK * MLPD];   // quantized activations (bf16 ints)
__device__ float g_as[NTOK];                  // per-token activation scales
__device__ float g_qkv[3 * NTOK * HID];       // q_t, k_t, v_t in [T, H*D] layout
__device__ float g_q[NTOK * HID];             // roped q, [B,H,S,D]
__device__ float g_k[NTOK * HID];             // roped k, [B,H,S,D]
__device__ float g_attno[NTOK * HID];         // attention output, [T, H*D]
__device__ float g_x1[NTOK * HID];            // residual after attention
__device__ float g_gate[NTOK * MLPD];
__device__ float g_up[NTOK * MLPD];
__device__ float g_down[NTOK * HID];

// ------------------------- weight quantization (bf16 out) -------------------------
__global__ void quant_w_kernel(const float* __restrict__ W,
                               const float* __restrict__ alpha,
                               __nv_bfloat16* __restrict__ Wq,
                               float* __restrict__ rs, int K) {
    int o = blockIdx.x;
    const float4* row = (const float4*)(W + (size_t)o * K);
    int nv = K / 4;
    __shared__ float red[256];
    float s = 0.f;
    for (int i = threadIdx.x; i < nv; i += 256) {
        float4 v = row[i];
        s += fabsf(v.x) + fabsf(v.y) + fabsf(v.z) + fabsf(v.w);
    }
    red[threadIdx.x] = s;
    __syncthreads();
    for (int st = 128; st > 0; st >>= 1) {
        if (threadIdx.x < st) red[threadIdx.x] += red[threadIdx.x + st];
        __syncthreads();
    }
    float wsc = red[0] / (float)K + 1e-8f;
    if (threadIdx.x == 0) rs[o] = wsc * alpha[o] / 127.0f;
    __nv_bfloat162* orow = (__nv_bfloat162*)(Wq + (size_t)o * K);
    for (int i = threadIdx.x; i < nv; i += 256) {
        float4 v = row[i];
        float q0 = fminf(fmaxf(rintf(v.x / wsc), -1.f), 1.f);
        float q1 = fminf(fmaxf(rintf(v.y / wsc), -1.f), 1.f);
        float q2 = fminf(fmaxf(rintf(v.z / wsc), -1.f), 1.f);
        float q3 = fminf(fmaxf(rintf(v.w / wsc), -1.f), 1.f);
        orow[i * 2 + 0] = __floats2bfloat162_rn(q0, q1);
        orow[i * 2 + 1] = __floats2bfloat162_rn(q2, q3);
    }
}

// ------------------------- rmsnorm + activation quant (N = 2048, bf16 out) -------------------------
__global__ void rms_quant_kernel(const float* __restrict__ x,
                                 const float* __restrict__ w,
                                 __nv_bfloat16* __restrict__ aq,
                                 float* __restrict__ as_) {
    int t = blockIdx.x;
    const float* row = x + (size_t)t * HID;
    float v[8], h[8];
    float ss = 0.f;
#pragma unroll
    for (int j = 0; j < 8; j++) {
        v[j] = row[j * 256 + threadIdx.x];
        ss += v[j] * v[j];
    }
    __shared__ float red[256];
    red[threadIdx.x] = ss;
    __syncthreads();
    for (int st = 128; st > 0; st >>= 1) {
        if (threadIdx.x < st) red[threadIdx.x] += red[threadIdx.x + st];
        __syncthreads();
    }
    float rms = sqrtf(red[0] / (float)HID + 1e-6f);
    __syncthreads();
    float mx = 0.f;
#pragma unroll
    for (int j = 0; j < 8; j++) {
        h[j] = v[j] / rms * w[j * 256 + threadIdx.x];
        mx = fmaxf(mx, fabsf(h[j]));
    }
    red[threadIdx.x] = mx;
    __syncthreads();
    for (int st = 128; st > 0; st >>= 1) {
        if (threadIdx.x < st) red[threadIdx.x] = fmaxf(red[threadIdx.x], red[threadIdx.x + st]);
        __syncthreads();
    }
    float asc = red[0] + 1e-8f;
    if (threadIdx.x == 0) as_[t] = asc;
    __nv_bfloat16* orow = aq + (size_t)t * HID;
#pragma unroll
    for (int j = 0; j < 8; j++) {
        float q = h[j] / asc * 127.0f;
        q = fminf(fmaxf(q, -128.f), 127.f);
        orow[j * 256 + threadIdx.x] = __float2bfloat16(rintf(q));
    }
}

// ------------------------- plain activation quant (generic N, bf16 out) -------------------------
__global__ void act_quant_kernel(const float* __restrict__ x,
                                 __nv_bfloat16* __restrict__ aq,
                                 float* __restrict__ as_, int N) {
    int t = blockIdx.x;
    const float* row = x + (size_t)t * N;
    __shared__ float red[256];
    float mx = 0.f;
    for (int i = threadIdx.x; i < N; i += 256) mx = fmaxf(mx, fabsf(row[i]));
    red[threadIdx.x] = mx;
    __syncthreads();
    for (int st = 128; st > 0; st >>= 1) {
        if (threadIdx.x < st) red[threadIdx.x] = fmaxf(red[threadIdx.x], red[threadIdx.x + st]);
        __syncthreads();
    }
    float asc = red[0] + 1e-8f;
    if (threadIdx.x == 0) as_[t] = asc;
    __nv_bfloat16* orow = aq + (size_t)t * N;
    for (int i = threadIdx.x; i < N; i += 256) {
        float q = row[i] / asc * 127.0f;
        q = fminf(fmaxf(q, -128.f), 127.f);
        orow[i] = __float2bfloat16(rintf(q));
    }
}

// ------------------------- fused add + rmsnorm + quant (N = 2048) -------------------------
__global__ void add_rms_quant_kernel(const float* __restrict__ x,
                                     const float* __restrict__ d,
                                     const float* __restrict__ w,
                                     float* __restrict__ x1,
                                     __nv_bfloat16* __restrict__ aq,
                                     float* __restrict__ as_) {
    int t = blockIdx.x;
    const float* rx = x + (size_t)t * HID;
    const float* rd = d + (size_t)t * HID;
    float* ro = x1 + (size_t)t * HID;
    float v[8], h[8];
    float ss = 0.f;
#pragma unroll
    for (int j = 0; j < 8; j++) {
        int idx = j * 256 + threadIdx.x;
        v[j] = rx[idx] + rd[idx];
        ro[idx] = v[j];
        ss += v[j] * v[j];
    }
    __shared__ float red[256];
    red[threadIdx.x] = ss;
    __syncthreads();
    for (int st = 128; st > 0; st >>= 1) {
        if (threadIdx.x < st) red[threadIdx.x] += red[threadIdx.x + st];
        __syncthreads();
    }
    float rms = sqrtf(red[0] / (float)HID + 1e-6f);
    __syncthreads();
    float mx = 0.f;
#pragma unroll
    for (int j = 0; j < 8; j++) {
        h[j] = v[j] / rms * w[j * 256 + threadIdx.x];
        mx = fmaxf(mx, fabsf(h[j]));
    }
    red[threadIdx.x] = mx;
    __syncthreads();
    for (int st = 128; st > 0; st >>= 1) {
        if (threadIdx.x < st) red[threadIdx.x] = fmaxf(red[threadIdx.x], red[threadIdx.x + st]);
        __syncthreads();
    }
    float asc = red[0] + 1e-8f;
    if (threadIdx.x == 0) as_[t] = asc;
    __nv_bfloat16* orow = aq + (size_t)t * HID;
#pragma unroll
    for (int j = 0; j < 8; j++) {
        float q = h[j] / asc * 127.0f;
        q = fminf(fmaxf(q, -128.f), 127.f);
        orow[j * 256 + threadIdx.x] = __float2bfloat16(rintf(q));
    }
}

// ------------------------- fused silu*up + quant (N = 8192) -------------------------
__global__ void __launch_bounds__(512)
silu_quant_kernel(const float* __restrict__ g, const float* __restrict__ u,
                  __nv_bfloat16* __restrict__ aq, float* __restrict__ as_) {
    int t = blockIdx.x;
    const float* rg = g + (size_t)t * MLPD;
    const float* ru = u + (size_t)t * MLPD;
    float v[16];
    float mx = 0.f;
#pragma unroll
    for (int j = 0; j < 16; j++) {
        int idx = j * 512 + threadIdx.x;
        float gx = rg[idx];
        float y = gx / (1.0f + __expf(-gx)) * ru[idx];
        v[j] = y;
        mx = fmaxf(mx, fabsf(y));
    }
    __shared__ float red[512];
    red[threadIdx.x] = mx;
    __syncthreads();
    for (int st = 256; st > 0; st >>= 1) {
        if (threadIdx.x < st) red[threadIdx.x] = fmaxf(red[threadIdx.x], red[threadIdx.x + st]);
        __syncthreads();
    }
    float asc = red[0] + 1e-8f;
    if (threadIdx.x == 0) as_[t] = asc;
    __nv_bfloat16* orow = aq + (size_t)t * MLPD;
#pragma unroll
    for (int j = 0; j < 16; j++) {
        float q = v[j] / asc * 127.0f;
        q = fminf(fmaxf(q, -128.f), 127.f);
        orow[j * 512 + threadIdx.x] = __float2bfloat16(rintf(q));
    }
}

// ------------------------- bf16 tensor-core GEMM (mma.sync, 3-stage) -------------------------
// C[t,o] = (sum_k A[t,k]*W[o,k]) * rs[o] * as[t]; A:[M,K] bf16, W:[N,K] bf16.
// 128x128x64 tile, 256 threads (8 warps as 4x2), 3-stage cp.async pipeline.
#define BM 128
#define BN 128
#define BK 64
#define NSTG 3
#define STG_BYTES 32768      // (BM + BN) * BK * 2

__device__ __forceinline__ unsigned smem_addr(const void* p) {
    return (unsigned)__cvta_generic_to_shared(p);
}
__device__ __forceinline__ void cp_async16(void* dst, const void* src) {
    asm volatile("cp.async.cg.shared.global [%0], [%1], 16;\n"
                 :: "r"(smem_addr(dst)), "l"(src));
}
__device__ __forceinline__ void cp_commit() { asm volatile("cp.async.commit_group;\n"); }
__device__ __forceinline__ void ldm4(unsigned* r, unsigned addr) {
    asm volatile("ldmatrix.sync.aligned.m8n8.x4.shared.b16 {%0,%1,%2,%3}, [%4];\n"
                 : "=r"(r[0]), "=r"(r[1]), "=r"(r[2]), "=r"(r[3]) : "r"(addr));
}
__device__ __forceinline__ void mma16816(float* c, const unsigned* a, unsigned b0, unsigned b1) {
    asm volatile(
        "mma.sync.aligned.m16n8k16.row.col.f32.bf16.bf16.f32 "
        "{%0,%1,%2,%3},{%4,%5,%6,%7},{%8,%9},{%0,%1,%2,%3};\n"
        : "+f"(c[0]), "+f"(c[1]), "+f"(c[2]), "+f"(c[3])
        : "r"(a[0]), "r"(a[1]), "r"(a[2]), "r"(a[3]), "r"(b0), "r"(b1));
}
// swizzled bf16 offset inside a [rows][BK] tile (BK=64: 8 units of 16B per row)
__device__ __forceinline__ int sw_off(int row, int u) {
    return (row * 8 + (u ^ (row & 7))) * 8;
}

__global__ void __launch_bounds__(256)
gemm_bf16_kernel(const __nv_bfloat16* __restrict__ A, const __nv_bfloat16* __restrict__ B,
                 const float* __restrict__ rs, const float* __restrict__ asc,
                 float* __restrict__ C, int K, int N) {
    extern __shared__ __nv_bfloat16 sm[];

    const int tid = threadIdx.x;
    const int lane = tid & 31;
    const int wid = tid >> 5;
    const int warp_m = wid >> 1;            // 0..3
    const int warp_n = wid & 1;             // 0..1
    const int rowBase = blockIdx.y * BM;
    const int colBase = blockIdx.x * BN;

    float acc[2][8][4];
#pragma unroll
    for (int mt = 0; mt < 2; mt++)
#pragma unroll
        for (int nt = 0; nt < 8; nt++)
#pragma unroll
            for (int i = 0; i < 4; i++) acc[mt][nt][i] = 0.f;

    const int nsteps = K / BK;
    const int lrow = tid >> 3, lu = tid & 7;   // per-thread load coords (rows step by 32)

    // prologue: stages 0 and 1
#pragma unroll
    for (int st = 0; st < NSTG - 1; st++) {
        __nv_bfloat16* Ab = sm + st * (STG_BYTES / 2);
        __nv_bfloat16* Bb = Ab + BM * BK;
        int k0 = st * BK;
#pragma unroll
        for (int it = 0; it < 4; it++) {
            int row = lrow + it * 32;
            cp_async16(Ab + sw_off(row, lu), A + (size_t)(rowBase + row) * K + k0 + lu * 8);
            cp_async16(Bb + sw_off(row, lu), B + (size_t)(colBase + row) * K + k0 + lu * 8);
        }
        cp_commit();
    }

    for (int s = 0; s < nsteps; s++) {
        asm volatile("cp.async.wait_group %0;\n" :: "n"(NSTG - 2));
        __syncthreads();

        // prefetch stage s+2
        if (s + NSTG - 1 < nsteps) {
            int st = (s + NSTG - 1) % NSTG;
            __nv_bfloat16* Ab = sm + st * (STG_BYTES / 2);
            __nv_bfloat16* Bb = Ab + BM * BK;
            int k0 = (s + NSTG - 1) * BK;
#pragma unroll
            for (int it = 0; it < 4; it++) {
                int row = lrow + it * 32;
                cp_async16(Ab + sw_off(row, lu), A + (size_t)(rowBase + row) * K + k0 + lu * 8);
                cp_async16(Bb + sw_off(row, lu), B + (size_t)(colBase + row) * K + k0 + lu * 8);
            }
            cp_commit();
        } else {
            cp_commit();   // keep group count in sync for wait_group
        }

        const int st = s % NSTG;
        const __nv_bfloat16* Ab = sm + st * (STG_BYTES / 2);
        const __nv_bfloat16* Bb = Ab + BM * BK;
        const unsigned a_base = smem_addr(Ab);
        const unsigned b_base = smem_addr(Bb);

#pragma unroll
        for (int kc = 0; kc < 4; kc++) {
            const int u = kc * 2 + (lane >> 4);
            unsigned afrag[2][4];
#pragma unroll
            for (int mt = 0; mt < 2; mt++) {
                int row = warp_m * 32 + mt * 16 + (lane & 15);
                ldm4(afrag[mt], a_base + (unsigned)sw_off(row, u) * 2);
            }
            unsigned bfrag[8][2];
#pragma unroll
            for (int np = 0; np < 4; np++) {
                int row = warp_n * 64 + np * 16 + (lane & 15);
                unsigned r[4];
                ldm4(r, b_base + (unsigned)sw_off(row, u) * 2);
                bfrag[np * 2 + 0][0] = r[0]; bfrag[np * 2 + 0][1] = r[2];
                bfrag[np * 2 + 1][0] = r[1]; bfrag[np * 2 + 1][1] = r[3];
            }
#pragma unroll
            for (int mt = 0; mt < 2; mt++)
#pragma unroll
                for (int nt = 0; nt < 8; nt++)
                    mma16816(acc[mt][nt], afrag[mt], bfrag[nt][0], bfrag[nt][1]);
        }
    }

    // epilogue with scales
#pragma unroll
    for (int mt = 0; mt < 2; mt++) {
        int r0 = rowBase + warp_m * 32 + mt * 16 + (lane >> 2);
        float sA = asc[r0], sB = asc[r0 + 8];
#pragma unroll
        for (int nt = 0; nt < 8; nt++) {
            int c0 = colBase + warp_n * 64 + nt * 8 + (lane & 3) * 2;
            float rs0 = rs[c0], rs1 = rs[c0 + 1];
            C[(size_t)r0 * N + c0]           = acc[mt][nt][0] * rs0 * sA;
            C[(size_t)r0 * N + c0 + 1]       = acc[mt][nt][1] * rs1 * sA;
            C[(size_t)(r0 + 8) * N + c0]     = acc[mt][nt][2] * rs0 * sB;
            C[(size_t)(r0 + 8) * N + c0 + 1] = acc[mt][nt][3] * rs1 * sB;
        }
    }
}

// ------------------------- RoPE + [T,H*D] -> [B,H,S,D] transpose for q,k -------------------------
__global__ void rope_kernel(const float* __restrict__ qt, const float* __restrict__ kt,
                            float* __restrict__ qo, float* __restrict__ ko) {
    int idx = blockIdx.x * blockDim.x + threadIdx.x;
    if (idx >= NTOK * NH * 64) return;
    int d = idx & 63;
    int th = idx >> 6;
    int h = th & (NH - 1);
    int t = th >> 4;
    int s = t & (SEQL - 1);
    int b = t >> 11;
    float invf = 1.0f / powf(10000.0f, (float)d / 64.0f);
    float ang = (float)s * invf;
    float sn, c;
    sincosf(ang, &sn, &c);
    size_t in0 = (size_t)t * HID + h * HD + d;
    size_t ob = ((size_t)(b * NH + h) * SEQL + s) * (size_t)HD + d;
    float x1 = qt[in0], x2 = qt[in0 + 64];
    qo[ob] = x1 * c - x2 * sn;
    qo[ob + 64] = x2 * c + x1 * sn;
    float y1 = kt[in0], y2 = kt[in0 + 64];
    ko[ob] = y1 * c - y2 * sn;
    ko[ob + 64] = y2 * c + y1 * sn;
}

// ------------------------- fused causal attention -------------------------
__global__ void __launch_bounds__(256)
attn_kernel(const float* __restrict__ q, const float* __restrict__ k,
            const float* __restrict__ vt, const int* __restrict__ mask,
            float* __restrict__ out) {
    __shared__ float Ks[32 * HD];
    __shared__ float Vs[32 * HD];
    const int wid = threadIdx.x >> 5;
    const int lane = threadIdx.x & 31;
    const int R = blockIdx.x * 8;
    const int s_base = R & (SEQL - 1);
    const int bh = R >> 11;
    const int h = bh & (NH - 1);
    const int b = bh >> 4;
    const int s = s_base + wid;

    const float* qrow = q + ((size_t)bh * SEQL + s) * HD;
    float q0 = qrow[lane], q1 = qrow[lane + 32], q2 = qrow[lane + 64], q3 = qrow[lane + 96];
    const float* kb = k + (size_t)bh * SEQL * HD;
    const float* vb = vt + (size_t)b * SEQL * HID + (size_t)h * HD;
    const int* mrow = mask + b * SEQL;

    float m = -1e30f, l = 0.f, a0 = 0.f, a1 = 0.f, a2 = 0.f, a3 = 0.f;
    const float scale = 0.08838834764831845f;
    const int jmax = s_base + 8;

    for (int j0 = 0; j0 < jmax; j0 += 32) {
        __syncthreads();
        int nk = min(32, jmax - j0);
        for (int i = threadIdx.x; i < nk * HD; i += 256) {
            Ks[i] = kb[(size_t)j0 * HD + i];
            int kj = i >> 7, d = i & 127;
            Vs[i] = vb[(size_t)(j0 + kj) * HID + d];
        }
        __syncthreads();
        int jend = min(nk, s - j0 + 1);
        for (int jj = 0; jj < jend; jj++) {
            const float* kr = Ks + jj * HD;
            float dot = q0 * kr[lane] + q1 * kr[lane + 32] + q2 * kr[lane + 64] + q3 * kr[lane + 96];
            dot += __shfl_xor_sync(0xffffffffu, dot, 16);
            dot += __shfl_xor_sync(0xffffffffu, dot, 8);
            dot += __shfl_xor_sync(0xffffffffu, dot, 4);
            dot += __shfl_xor_sync(0xffffffffu, dot, 2);
            dot += __shfl_xor_sync(0xffffffffu, dot, 1);
            float sc = dot * scale;
            sc = (mrow[j0 + jj] == 0) ? -10000.f : fmaxf(sc, -10000.f);
            float nm = fmaxf(m, sc);
            float cor = __expf(m - nm);
            float p = __expf(sc - nm);
            l = l * cor + p;
            const float* vr = Vs + jj * HD;
            a0 = a0 * cor + p * vr[lane];
            a1 = a1 * cor + p * vr[lane + 32];
            a2 = a2 * cor + p * vr[lane + 64];
            a3 = a3 * cor + p * vr[lane + 96];
            m = nm;
        }
    }
    float inv = 1.f / l;
    size_t ob = ((size_t)b * SEQL + s) * HID + (size_t)h * HD;
    out[ob + lane] = a0 * inv;
    out[ob + lane + 32] = a1 * inv;
    out[ob + lane + 64] = a2 * inv;
    out[ob + lane + 96] = a3 * inv;
}

// ------------------------- elementwise -------------------------
__global__ void add_kernel(const float* __restrict__ a, const float* __restrict__ b,
                           float* __restrict__ c, int n) {
    int i = blockIdx.x * blockDim.x + threadIdx.x;
    if (i < n) c[i] = a[i] + b[i];
}

// ------------------------- host orchestration -------------------------
extern "C" void kernel_launch(void* const* d_in, const int* in_sizes, int n_in,
                              void* d_out, int out_size) {
    const float* x     = (const float*)d_in[0];
    const int*   amask = (const int*)d_in[1];
    const float* wq = (const float*)d_in[2];   const float* aq_a = (const float*)d_in[3];
    const float* wk = (const float*)d_in[4];   const float* ak_a = (const float*)d_in[5];
    const float* wv = (const float*)d_in[6];   const float* av_a = (const float*)d_in[7];
    const float* wo = (const float*)d_in[8];   const float* ao_a = (const float*)d_in[9];
    const float* wg = (const float*)d_in[10];  const float* ag_a = (const float*)d_in[11];
    const float* wu = (const float*)d_in[12];  const float* au_a = (const float*)d_in[13];
    const float* wd = (const float*)d_in[14];  const float* ad_a = (const float*)d_in[15];
    const float* n1 = (const float*)d_in[16];
    const float* n2 = (const float*)d_in[17];
    float* out = (float*)d_out;

    __nv_bfloat16 *p_wq, *p_wk, *p_wv, *p_wo, *p_wg, *p_wu, *p_wd, *p_aq;
    float *p_sq, *p_sk, *p_sv, *p_so, *p_sg, *p_su, *p_sd;
    float *p_as, *p_qkv, *p_q, *p_k, *p_attno, *p_x1, *p_gate, *p_up, *p_down;
    cudaGetSymbolAddress((void**)&p_wq, g_wq);
    cudaGetSymbolAddress((void**)&p_wk, g_wk);
    cudaGetSymbolAddress((void**)&p_wv, g_wv);
    cudaGetSymbolAddress((void**)&p_wo, g_wo);
    cudaGetSymbolAddress((void**)&p_wg, g_wg);
    cudaGetSymbolAddress((void**)&p_wu, g_wu);
    cudaGetSymbolAddress((void**)&p_wd, g_wd);
    cudaGetSymbolAddress((void**)&p_sq, g_sq);
    cudaGetSymbolAddress((void**)&p_sk, g_sk);
    cudaGetSymbolAddress((void**)&p_sv, g_sv);
    cudaGetSymbolAddress((void**)&p_so, g_so);
    cudaGetSymbolAddress((void**)&p_sg, g_sg);
    cudaGetSymbolAddress((void**)&p_su, g_su);
    cudaGetSymbolAddress((void**)&p_sd, g_sd);
    cudaGetSymbolAddress((void**)&p_aq, g_aq);
    cudaGetSymbolAddress((void**)&p_as, g_as);
    cudaGetSymbolAddress((void**)&p_qkv, g_qkv);
    cudaGetSymbolAddress((void**)&p_q, g_q);
    cudaGetSymbolAddress((void**)&p_k, g_k);
    cudaGetSymbolAddress((void**)&p_attno, g_attno);
    cudaGetSymbolAddress((void**)&p_x1, g_x1);
    cudaGetSymbolAddress((void**)&p_gate, g_gate);
    cudaGetSymbolAddress((void**)&p_up, g_up);
    cudaGetSymbolAddress((void**)&p_down, g_down);

    const int smem_bytes = NSTG * STG_BYTES;   // 98304
    cudaFuncSetAttribute(gemm_bf16_kernel, cudaFuncAttributeMaxDynamicSharedMemorySize, smem_bytes);

    // 1) quantize all weights (bf16)
    quant_w_kernel<<<HID, 256>>>(wq, aq_a, p_wq, p_sq, HID);
    quant_w_kernel<<<HID, 256>>>(wk, ak_a, p_wk, p_sk, HID);
    quant_w_kernel<<<HID, 256>>>(wv, av_a, p_wv, p_sv, HID);
    quant_w_kernel<<<HID, 256>>>(wo, ao_a, p_wo, p_so, HID);
    quant_w_kernel<<<MLPD, 256>>>(wg, ag_a, p_wg, p_sg, HID);
    quant_w_kernel<<<MLPD, 256>>>(wu, au_a, p_wu, p_su, HID);
    quant_w_kernel<<<HID, 256>>>(wd, ad_a, p_wd, p_sd, MLPD);

    // 2) rmsnorm + quantize input
    rms_quant_kernel<<<NTOK, 256>>>(x, n1, p_aq, p_as);

    // 3) q,k,v projections
    dim3 g16(HID / BN, NTOK / BM);
    gemm_bf16_kernel<<<g16, 256, smem_bytes>>>(p_aq, p_wq, p_sq, p_as, p_qkv, HID, HID);
    gemm_bf16_kernel<<<g16, 256, smem_bytes>>>(p_aq, p_wk, p_sk, p_as, p_qkv + (size_t)NTOK * HID, HID, HID);
    gemm_bf16_kernel<<<g16, 256, smem_bytes>>>(p_aq, p_wv, p_sv, p_as, p_qkv + 2 * (size_t)NTOK * HID, HID, HID);

    // 4) rope + transpose q,k
    rope_kernel<<<(NTOK * NH * 64 + 255) / 256, 256>>>(p_qkv, p_qkv + (size_t)NTOK * HID, p_q, p_k);

    // 5) attention
    attn_kernel<<<NTOK * NH / 8, 256>>>(p_q, p_k, p_qkv + 2 * (size_t)NTOK * HID, amask, p_attno);

    // 6) output projection
    act_quant_kernel<<<NTOK, 256>>>(p_attno, p_aq, p_as, HID);
    gemm_bf16_kernel<<<g16, 256, smem_bytes>>>(p_aq, p_wo, p_so, p_as, p_down, HID, HID);

    // 7) residual + rmsnorm + quant (fused)
    add_rms_quant_kernel<<<NTOK, 256>>>(x, p_down, n2, p_x1, p_aq, p_as);

    // 8) MLP
    dim3 g64(MLPD / BN, NTOK / BM);
    gemm_bf16_kernel<<<g64, 256, smem_bytes>>>(p_aq, p_wg, p_sg, p_as, p_gate, HID, MLPD);
    gemm_bf16_kernel<<<g64, 256, smem_bytes>>>(p_aq, p_wu, p_su, p_as, p_up, HID, MLPD);
    silu_quant_kernel<<<NTOK, 512>>>(p_gate, p_up, p_aq, p_as);
    gemm_bf16_kernel<<<g16, 256, smem_bytes>>>(p_aq, p_wd, p_sd, p_as, p_down, MLPD, HID);

    // 9) final residual into d_out
    add_kernel<<<NTOK * HID / 256, 256>>>(p_x1, p_down, out, NTOK * HID);
    (void)in_sizes; (void)n_in; (void)out_size;
}

// round 8
// speedup vs baseline: 5.3663x; 5.3663x over previous
#include <cuda_runtime.h>
#include <cuda_bf16.h>
#include <cuda_fp16.h>
#include <cstdint>
#include <stdint.h>
#include <math.h>

#define NTOK   4096      // B*S
#define HID    2048
#define NH     16
#define HD     128
#define MLPD   8192
#define SEQL   2048

// ------------------------- persistent device scratch -------------------------
__device__ __nv_bfloat16 g_wq[HID * HID];
__device__ __nv_bfloat16 g_wk[HID * HID];
__device__ __nv_bfloat16 g_wv[HID * HID];
__device__ __nv_bfloat16 g_wo[HID * HID];
__device__ __nv_bfloat16 g_wg[MLPD * HID];
__device__ __nv_bfloat16 g_wu[MLPD * HID];
__device__ __nv_bfloat16 g_wd[HID * MLPD];
__device__ float g_sq[HID], g_sk[HID], g_sv[HID], g_so[HID];
__device__ float g_sg[MLPD], g_su[MLPD], g_sd[HID];

__device__ __nv_bfloat16 g_aq[NTOK * MLPD];   // quantized activations (bf16 ints)
__device__ float g_as[NTOK];                  // per-token activation scales
__device__ float g_qkv[3 * NTOK * HID];       // q_t, k_t, v_t in [T, H*D] layout
__device__ __half g_qh[NTOK * HID];           // roped q fp16, [B,H,S,D]
__device__ __half g_kh[NTOK * HID];           // roped k fp16, [B,H,S,D]
__device__ __half g_vh[NTOK * HID];           // v fp16, [B,H,S,D]
__device__ float g_attno[NTOK * HID];         // attention output, [T, H*D]
__device__ float g_x1[NTOK * HID];            // residual after attention
__device__ float g_gate[NTOK * MLPD];
__device__ float g_up[NTOK * MLPD];
__device__ float g_down[NTOK * HID];

// ------------------------- weight quantization (bf16 out) -------------------------
__global__ void quant_w_kernel(const float* __restrict__ W,
                               const float* __restrict__ alpha,
                               __nv_bfloat16* __restrict__ Wq,
                               float* __restrict__ rs, int K) {
    int o = blockIdx.x;
    const float4* row = (const float4*)(W + (size_t)o * K);
    int nv = K / 4;
    __shared__ float red[256];
    float s = 0.f;
    for (int i = threadIdx.x; i < nv; i += 256) {
        float4 v = row[i];
        s += fabsf(v.x) + fabsf(v.y) + fabsf(v.z) + fabsf(v.w);
    }
    red[threadIdx.x] = s;
    __syncthreads();
    for (int st = 128; st > 0; st >>= 1) {
        if (threadIdx.x < st) red[threadIdx.x] += red[threadIdx.x + st];
        __syncthreads();
    }
    float wsc = red[0] / (float)K + 1e-8f;
    if (threadIdx.x == 0) rs[o] = wsc * alpha[o] / 127.0f;
    __nv_bfloat162* orow = (__nv_bfloat162*)(Wq + (size_t)o * K);
    for (int i = threadIdx.x; i < nv; i += 256) {
        float4 v = row[i];
        float q0 = fminf(fmaxf(rintf(v.x / wsc), -1.f), 1.f);
        float q1 = fminf(fmaxf(rintf(v.y / wsc), -1.f), 1.f);
        float q2 = fminf(fmaxf(rintf(v.z / wsc), -1.f), 1.f);
        float q3 = fminf(fmaxf(rintf(v.w / wsc), -1.f), 1.f);
        orow[i * 2 + 0] = __floats2bfloat162_rn(q0, q1);
        orow[i * 2 + 1] = __floats2bfloat162_rn(q2, q3);
    }
}

// ------------------------- rmsnorm + activation quant (N = 2048, bf16 out) -------------------------
__global__ void rms_quant_kernel(const float* __restrict__ x,
                                 const float* __restrict__ w,
                                 __nv_bfloat16* __restrict__ aq,
                                 float* __restrict__ as_) {
    int t = blockIdx.x;
    const float* row = x + (size_t)t * HID;
    float v[8], h[8];
    float ss = 0.f;
#pragma unroll
    for (int j = 0; j < 8; j++) {
        v[j] = row[j * 256 + threadIdx.x];
        ss += v[j] * v[j];
    }
    __shared__ float red[256];
    red[threadIdx.x] = ss;
    __syncthreads();
    for (int st = 128; st > 0; st >>= 1) {
        if (threadIdx.x < st) red[threadIdx.x] += red[threadIdx.x + st];
        __syncthreads();
    }
    float rms = sqrtf(red[0] / (float)HID + 1e-6f);
    __syncthreads();
    float mx = 0.f;
#pragma unroll
    for (int j = 0; j < 8; j++) {
        h[j] = v[j] / rms * w[j * 256 + threadIdx.x];
        mx = fmaxf(mx, fabsf(h[j]));
    }
    red[threadIdx.x] = mx;
    __syncthreads();
    for (int st = 128; st > 0; st >>= 1) {
        if (threadIdx.x < st) red[threadIdx.x] = fmaxf(red[threadIdx.x], red[threadIdx.x + st]);
        __syncthreads();
    }
    float asc = red[0] + 1e-8f;
    if (threadIdx.x == 0) as_[t] = asc;
    __nv_bfloat16* orow = aq + (size_t)t * HID;
#pragma unroll
    for (int j = 0; j < 8; j++) {
        float q = h[j] / asc * 127.0f;
        q = fminf(fmaxf(q, -128.f), 127.f);
        orow[j * 256 + threadIdx.x] = __float2bfloat16(rintf(q));
    }
}

// ------------------------- plain activation quant (generic N, bf16 out) -------------------------
__global__ void act_quant_kernel(const float* __restrict__ x,
                                 __nv_bfloat16* __restrict__ aq,
                                 float* __restrict__ as_, int N) {
    int t = blockIdx.x;
    const float* row = x + (size_t)t * N;
    __shared__ float red[256];
    float mx = 0.f;
    for (int i = threadIdx.x; i < N; i += 256) mx = fmaxf(mx, fabsf(row[i]));
    red[threadIdx.x] = mx;
    __syncthreads();
    for (int st = 128; st > 0; st >>= 1) {
        if (threadIdx.x < st) red[threadIdx.x] = fmaxf(red[threadIdx.x], red[threadIdx.x + st]);
        __syncthreads();
    }
    float asc = red[0] + 1e-8f;
    if (threadIdx.x == 0) as_[t] = asc;
    __nv_bfloat16* orow = aq + (size_t)t * N;
    for (int i = threadIdx.x; i < N; i += 256) {
        float q = row[i] / asc * 127.0f;
        q = fminf(fmaxf(q, -128.f), 127.f);
        orow[i] = __float2bfloat16(rintf(q));
    }
}

// ------------------------- fused add + rmsnorm + quant (N = 2048) -------------------------
__global__ void add_rms_quant_kernel(const float* __restrict__ x,
                                     const float* __restrict__ d,
                                     const float* __restrict__ w,
                                     float* __restrict__ x1,
                                     __nv_bfloat16* __restrict__ aq,
                                     float* __restrict__ as_) {
    int t = blockIdx.x;
    const float* rx = x + (size_t)t * HID;
    const float* rd = d + (size_t)t * HID;
    float* ro = x1 + (size_t)t * HID;
    float v[8], h[8];
    float ss = 0.f;
#pragma unroll
    for (int j = 0; j < 8; j++) {
        int idx = j * 256 + threadIdx.x;
        v[j] = rx[idx] + rd[idx];
        ro[idx] = v[j];
        ss += v[j] * v[j];
    }
    __shared__ float red[256];
    red[threadIdx.x] = ss;
    __syncthreads();
    for (int st = 128; st > 0; st >>= 1) {
        if (threadIdx.x < st) red[threadIdx.x] += red[threadIdx.x + st];
        __syncthreads();
    }
    float rms = sqrtf(red[0] / (float)HID + 1e-6f);
    __syncthreads();
    float mx = 0.f;
#pragma unroll
    for (int j = 0; j < 8; j++) {
        h[j] = v[j] / rms * w[j * 256 + threadIdx.x];
        mx = fmaxf(mx, fabsf(h[j]));
    }
    red[threadIdx.x] = mx;
    __syncthreads();
    for (int st = 128; st > 0; st >>= 1) {
        if (threadIdx.x < st) red[threadIdx.x] = fmaxf(red[threadIdx.x], red[threadIdx.x + st]);
        __syncthreads();
    }
    float asc = red[0] + 1e-8f;
    if (threadIdx.x == 0) as_[t] = asc;
    __nv_bfloat16* orow = aq + (size_t)t * HID;
#pragma unroll
    for (int j = 0; j < 8; j++) {
        float q = h[j] / asc * 127.0f;
        q = fminf(fmaxf(q, -128.f), 127.f);
        orow[j * 256 + threadIdx.x] = __float2bfloat16(rintf(q));
    }
}

// ------------------------- fused silu*up + quant (N = 8192) -------------------------
__global__ void __launch_bounds__(512)
silu_quant_kernel(const float* __restrict__ g, const float* __restrict__ u,
                  __nv_bfloat16* __restrict__ aq, float* __restrict__ as_) {
    int t = blockIdx.x;
    const float* rg = g + (size_t)t * MLPD;
    const float* ru = u + (size_t)t * MLPD;
    float v[16];
    float mx = 0.f;
#pragma unroll
    for (int j = 0; j < 16; j++) {
        int idx = j * 512 + threadIdx.x;
        float gx = rg[idx];
        float y = gx / (1.0f + __expf(-gx)) * ru[idx];
        v[j] = y;
        mx = fmaxf(mx, fabsf(y));
    }
    __shared__ float red[512];
    red[threadIdx.x] = mx;
    __syncthreads();
    for (int st = 256; st > 0; st >>= 1) {
        if (threadIdx.x < st) red[threadIdx.x] = fmaxf(red[threadIdx.x], red[threadIdx.x + st]);
        __syncthreads();
    }
    float asc = red[0] + 1e-8f;
    if (threadIdx.x == 0) as_[t] = asc;
    __nv_bfloat16* orow = aq + (size_t)t * MLPD;
#pragma unroll
    for (int j = 0; j < 16; j++) {
        float q = v[j] / asc * 127.0f;
        q = fminf(fmaxf(q, -128.f), 127.f);
        orow[j * 512 + threadIdx.x] = __float2bfloat16(rintf(q));
    }
}

// ------------------------- mma helpers -------------------------
__device__ __forceinline__ unsigned smem_addr(const void* p) {
    return (unsigned)__cvta_generic_to_shared(p);
}
__device__ __forceinline__ void cp_async16(void* dst, const void* src) {
    asm volatile("cp.async.cg.shared.global [%0], [%1], 16;\n"
                 :: "r"(smem_addr(dst)), "l"(src));
}
__device__ __forceinline__ void cp_commit() { asm volatile("cp.async.commit_group;\n"); }
__device__ __forceinline__ void ldm4(unsigned* r, unsigned addr) {
    asm volatile("ldmatrix.sync.aligned.m8n8.x4.shared.b16 {%0,%1,%2,%3}, [%4];\n"
                 : "=r"(r[0]), "=r"(r[1]), "=r"(r[2]), "=r"(r[3]) : "r"(addr));
}
__device__ __forceinline__ void ldm4t(unsigned* r, unsigned addr) {
    asm volatile("ldmatrix.sync.aligned.m8n8.x4.trans.shared.b16 {%0,%1,%2,%3}, [%4];\n"
                 : "=r"(r[0]), "=r"(r[1]), "=r"(r[2]), "=r"(r[3]) : "r"(addr));
}
__device__ __forceinline__ void mma16816(float* c, const unsigned* a, unsigned b0, unsigned b1) {
    asm volatile(
        "mma.sync.aligned.m16n8k16.row.col.f32.bf16.bf16.f32 "
        "{%0,%1,%2,%3},{%4,%5,%6,%7},{%8,%9},{%0,%1,%2,%3};\n"
        : "+f"(c[0]), "+f"(c[1]), "+f"(c[2]), "+f"(c[3])
        : "r"(a[0]), "r"(a[1]), "r"(a[2]), "r"(a[3]), "r"(b0), "r"(b1));
}
__device__ __forceinline__ void mma16816h(float* c, const unsigned* a, unsigned b0, unsigned b1) {
    asm volatile(
        "mma.sync.aligned.m16n8k16.row.col.f32.f16.f16.f32 "
        "{%0,%1,%2,%3},{%4,%5,%6,%7},{%8,%9},{%0,%1,%2,%3};\n"
        : "+f"(c[0]), "+f"(c[1]), "+f"(c[2]), "+f"(c[3])
        : "r"(a[0]), "r"(a[1]), "r"(a[2]), "r"(a[3]), "r"(b0), "r"(b1));
}
__device__ __forceinline__ unsigned packh2(float a, float b) {
    __half2 h = __floats2half2_rn(a, b);
    return *reinterpret_cast<unsigned*>(&h);
}

// ------------------------- bf16 tensor-core GEMM (Round-3 validated) -------------------------
#define BM 128
#define BN 128
#define BK 64
// swizzled bf16 offset inside a [rows][BK] tile (BK=64: 8 units of 16B per row)
__device__ __forceinline__ int sw_off(int row, int u) {
    return (row * 8 + (u ^ (row & 7))) * 8;
}

__global__ void __launch_bounds__(256)
gemm_bf16_kernel(const __nv_bfloat16* __restrict__ A, const __nv_bfloat16* __restrict__ B,
                 const float* __restrict__ rs, const float* __restrict__ asc,
                 float* __restrict__ C, int K, int N) {
    extern __shared__ __nv_bfloat16 sm[];
    __nv_bfloat16* As = sm;                 // 2 * BM * BK
    __nv_bfloat16* Bs = sm + 2 * BM * BK;   // 2 * BN * BK

    const int tid = threadIdx.x;
    const int lane = tid & 31;
    const int wid = tid >> 5;
    const int warp_m = wid >> 1;            // 0..3
    const int warp_n = wid & 1;             // 0..1
    const int rowBase = blockIdx.y * BM;
    const int colBase = blockIdx.x * BN;

    float acc[2][8][4];
#pragma unroll
    for (int mt = 0; mt < 2; mt++)
#pragma unroll
        for (int nt = 0; nt < 8; nt++)
#pragma unroll
            for (int i = 0; i < 4; i++) acc[mt][nt][i] = 0.f;

    const int nsteps = K / BK;
    {
        __nv_bfloat16* Ab = As;
        __nv_bfloat16* Bb = Bs;
#pragma unroll
        for (int it = 0; it < 4; it++) {
            int j = tid + it * 256;
            int row = j >> 3, u = j & 7;
            cp_async16(Ab + sw_off(row, u), A + (size_t)(rowBase + row) * K + u * 8);
            cp_async16(Bb + sw_off(row, u), B + (size_t)(colBase + row) * K + u * 8);
        }
        cp_commit();
    }

    for (int s = 0; s < nsteps; s++) {
        if (s + 1 < nsteps) {
            __nv_bfloat16* Ab = As + ((s + 1) & 1) * BM * BK;
            __nv_bfloat16* Bb = Bs + ((s + 1) & 1) * BN * BK;
            int k0 = (s + 1) * BK;
#pragma unroll
            for (int it = 0; it < 4; it++) {
                int j = tid + it * 256;
                int row = j >> 3, u = j & 7;
                cp_async16(Ab + sw_off(row, u), A + (size_t)(rowBase + row) * K + k0 + u * 8);
                cp_async16(Bb + sw_off(row, u), B + (size_t)(colBase + row) * K + k0 + u * 8);
            }
            cp_commit();
            asm volatile("cp.async.wait_group 1;\n");
        } else {
            asm volatile("cp.async.wait_group 0;\n");
        }
        __syncthreads();

        const __nv_bfloat16* Ab = As + (s & 1) * BM * BK;
        const __nv_bfloat16* Bb = Bs + (s & 1) * BN * BK;
        const unsigned a_base = smem_addr(Ab);
        const unsigned b_base = smem_addr(Bb);

#pragma unroll
        for (int kc = 0; kc < 4; kc++) {
            const int u = kc * 2 + (lane >> 4);
            unsigned afrag[2][4];
#pragma unroll
            for (int mt = 0; mt < 2; mt++) {
                int row = warp_m * 32 + mt * 16 + (lane & 15);
                ldm4(afrag[mt], a_base + (unsigned)sw_off(row, u) * 2);
            }
            unsigned bfrag[8][2];
#pragma unroll
            for (int np = 0; np < 4; np++) {
                int row = warp_n * 64 + np * 16 + (lane & 15);
                unsigned r[4];
                ldm4(r, b_base + (unsigned)sw_off(row, u) * 2);
                bfrag[np * 2 + 0][0] = r[0]; bfrag[np * 2 + 0][1] = r[2];
                bfrag[np * 2 + 1][0] = r[1]; bfrag[np * 2 + 1][1] = r[3];
            }
#pragma unroll
            for (int mt = 0; mt < 2; mt++)
#pragma unroll
                for (int nt = 0; nt < 8; nt++)
                    mma16816(acc[mt][nt], afrag[mt], bfrag[nt][0], bfrag[nt][1]);
        }
        __syncthreads();
    }

#pragma unroll
    for (int mt = 0; mt < 2; mt++) {
        int r0 = rowBase + warp_m * 32 + mt * 16 + (lane >> 2);
        float sA = asc[r0], sB = asc[r0 + 8];
#pragma unroll
        for (int nt = 0; nt < 8; nt++) {
            int c0 = colBase + warp_n * 64 + nt * 8 + (lane & 3) * 2;
            float rs0 = rs[c0], rs1 = rs[c0 + 1];
            C[(size_t)r0 * N + c0]           = acc[mt][nt][0] * rs0 * sA;
            C[(size_t)r0 * N + c0 + 1]       = acc[mt][nt][1] * rs1 * sA;
            C[(size_t)(r0 + 8) * N + c0]     = acc[mt][nt][2] * rs0 * sB;
            C[(size_t)(r0 + 8) * N + c0 + 1] = acc[mt][nt][3] * rs1 * sB;
        }
    }
}

// ------------------------- RoPE + transpose + fp16 convert for q,k,v -------------------------
__global__ void rope_half_kernel(const float* __restrict__ qt, const float* __restrict__ kt,
                                 const float* __restrict__ vt,
                                 __half* __restrict__ qo, __half* __restrict__ ko,
                                 __half* __restrict__ vo) {
    int idx = blockIdx.x * blockDim.x + threadIdx.x;
    if (idx >= NTOK * NH * 64) return;
    int d = idx & 63;
    int th = idx >> 6;
    int h = th & (NH - 1);
    int t = th >> 4;
    int s = t & (SEQL - 1);
    int b = t >> 11;
    float invf = 1.0f / powf(10000.0f, (float)d / 64.0f);
    float ang = (float)s * invf;
    float sn, c;
    sincosf(ang, &sn, &c);
    size_t in0 = (size_t)t * HID + h * HD + d;
    size_t ob = ((size_t)(b * NH + h) * SEQL + s) * (size_t)HD + d;
    float x1 = qt[in0], x2 = qt[in0 + 64];
    qo[ob] = __float2half(x1 * c - x2 * sn);
    qo[ob + 64] = __float2half(x2 * c + x1 * sn);
    float y1 = kt[in0], y2 = kt[in0 + 64];
    ko[ob] = __float2half(y1 * c - y2 * sn);
    ko[ob + 64] = __float2half(y2 * c + y1 * sn);
    vo[ob] = __float2half(vt[in0]);
    vo[ob + 64] = __float2half(vt[in0 + 64]);
}

// ------------------------- fp16 mma flash attention -------------------------
// block = 64 query rows of one (b,h); 4 warps x 16 rows; 64-key tiles, K/V double-buffered.
// sw16: swizzled half-offset in a [rows][128] half tile (16 units of 16B per row)
__device__ __forceinline__ int sw16(int row, int u) {
    return row * 128 + (((u ^ row) & 7) | (u & 8)) * 8;
}

__device__ __forceinline__ void attn_load_tile(__half* Ks, __half* Vs,
                                               const __half* kb_, const __half* vb_,
                                               int tid) {
#pragma unroll
    for (int it = 0; it < 8; it++) {
        int idx = tid + it * 128;
        int row = idx >> 4, u = idx & 15;
        cp_async16(Ks + sw16(row, u), kb_ + (size_t)row * HD + u * 8);
        cp_async16(Vs + sw16(row, u), vb_ + (size_t)row * HD + u * 8);
    }
}

__global__ void __launch_bounds__(128)
attn_mma_kernel(const __half* __restrict__ qh, const __half* __restrict__ kh,
                const __half* __restrict__ vh, const int* __restrict__ mask,
                float* __restrict__ out) {
    extern __shared__ __half ash[];
    __half* Qs = ash;                 // 8192 halfs
    __half* KsA[2] = {ash + 8192, ash + 16384};
    __half* VsA[2] = {ash + 24576, ash + 32768};

    const int tid = threadIdx.x;
    const int lane = tid & 31;
    const int wid = tid >> 5;
    const int bx = blockIdx.x;
    const int bh = bx & 31;           // b*16+h
    const int qslot = bx >> 5;
    const int qb = (31 - qslot) * 64; // longest blocks first
    const int b = bh >> 4;
    const int h = bh & 15;

    const __half* qbase = qh + ((size_t)bh * SEQL + qb) * HD;
    const __half* kbase = kh + (size_t)bh * SEQL * HD;
    const __half* vbase = vh + (size_t)bh * SEQL * HD;
    const int* mrow = mask + b * SEQL;
    const int ntiles = qb / 64 + 1;

    // prologue: Q + tile0, then tile1 (or empty)
#pragma unroll
    for (int it = 0; it < 8; it++) {
        int idx = tid + it * 128;
        int row = idx >> 4, u = idx & 15;
        cp_async16(Qs + sw16(row, u), qbase + (size_t)row * HD + u * 8);
    }
    attn_load_tile(KsA[0], VsA[0], kbase, vbase, tid);
    cp_commit();
    if (ntiles > 1) attn_load_tile(KsA[1], VsA[1], kbase + 64 * HD, vbase + 64 * HD, tid);
    cp_commit();

    float oacc[16][4];
#pragma unroll
    for (int i = 0; i < 16; i++) { oacc[i][0] = oacc[i][1] = oacc[i][2] = oacc[i][3] = 0.f; }
    float m0 = -1e30f, m1 = -1e30f, l0 = 0.f, l1 = 0.f;
    const float scale = 0.08838834764831845f;
    const int r = lane >> 2;
    const int c2 = (lane & 3) * 2;
    const int qr0 = qb + wid * 16 + r;    // row of c[0],c[1]; +8 for c[2],c[3]
    const unsigned qs_base = smem_addr(Qs);

    for (int t = 0; t < ntiles; t++) {
        asm volatile("cp.async.wait_group 1;\n");
        __syncthreads();
        const int kb = t * 64;
        const unsigned k_base = smem_addr(KsA[t & 1]);
        const unsigned v_base = smem_addr(VsA[t & 1]);

        // --- S = Q K^T (m16 per warp x n64 x k128) ---
        float sacc[8][4];
#pragma unroll
        for (int nt = 0; nt < 8; nt++) { sacc[nt][0] = sacc[nt][1] = sacc[nt][2] = sacc[nt][3] = 0.f; }
#pragma unroll
        for (int kc = 0; kc < 8; kc++) {
            const int u = kc * 2 + (lane >> 4);
            unsigned afrag[4];
            ldm4(afrag, qs_base + (unsigned)sw16(wid * 16 + (lane & 15), u) * 2);
#pragma unroll
            for (int np = 0; np < 4; np++) {
                unsigned rr[4];
                ldm4(rr, k_base + (unsigned)sw16(np * 16 + (lane & 15), u) * 2);
                mma16816h(sacc[np * 2 + 0], afrag, rr[0], rr[2]);
                mma16816h(sacc[np * 2 + 1], afrag, rr[1], rr[3]);
            }
        }

        // --- mask + online softmax ---
        float mx0 = -1e30f, mx1 = -1e30f;
#pragma unroll
        for (int nt = 0; nt < 8; nt++) {
#pragma unroll
            for (int i = 0; i < 4; i++) {
                int col = kb + nt * 8 + c2 + (i & 1);
                int qr = qr0 + ((i >> 1) << 3);
                float s = sacc[nt][i] * scale;
                bool dead = (col > qr) || (mrow[col] == 0);
                s = dead ? -10000.f : fmaxf(s, -10000.f);
                sacc[nt][i] = s;
                if (i < 2) mx0 = fmaxf(mx0, s); else mx1 = fmaxf(mx1, s);
            }
        }
        mx0 = fmaxf(mx0, __shfl_xor_sync(0xffffffffu, mx0, 1));
        mx0 = fmaxf(mx0, __shfl_xor_sync(0xffffffffu, mx0, 2));
        mx1 = fmaxf(mx1, __shfl_xor_sync(0xffffffffu, mx1, 1));
        mx1 = fmaxf(mx1, __shfl_xor_sync(0xffffffffu, mx1, 2));
        float nm0 = fmaxf(m0, mx0), nm1 = fmaxf(m1, mx1);
        float cor0 = __expf(m0 - nm0), cor1 = __expf(m1 - nm1);
        float ls0 = 0.f, ls1 = 0.f;
#pragma unroll
        for (int nt = 0; nt < 8; nt++) {
#pragma unroll
            for (int i = 0; i < 4; i++) {
                float p = __expf(sacc[nt][i] - ((i < 2) ? nm0 : nm1));
                sacc[nt][i] = p;
                if (i < 2) ls0 += p; else ls1 += p;
            }
        }
        ls0 += __shfl_xor_sync(0xffffffffu, ls0, 1);
        ls0 += __shfl_xor_sync(0xffffffffu, ls0, 2);
        ls1 += __shfl_xor_sync(0xffffffffu, ls1, 1);
        ls1 += __shfl_xor_sync(0xffffffffu, ls1, 2);
        l0 = l0 * cor0 + ls0;
        l1 = l1 * cor1 + ls1;
        m0 = nm0; m1 = nm1;
#pragma unroll
        for (int i = 0; i < 16; i++) {
            oacc[i][0] *= cor0; oacc[i][1] *= cor0;
            oacc[i][2] *= cor1; oacc[i][3] *= cor1;
        }

        // --- O += P V (k = 64 keys in 4 chunks, n = 128 dims) ---
#pragma unroll
        for (int kc2 = 0; kc2 < 4; kc2++) {
            unsigned pa[4];
            pa[0] = packh2(sacc[2 * kc2][0], sacc[2 * kc2][1]);
            pa[1] = packh2(sacc[2 * kc2][2], sacc[2 * kc2][3]);
            pa[2] = packh2(sacc[2 * kc2 + 1][0], sacc[2 * kc2 + 1][1]);
            pa[3] = packh2(sacc[2 * kc2 + 1][2], sacc[2 * kc2 + 1][3]);
#pragma unroll
            for (int dnp = 0; dnp < 8; dnp++) {
                unsigned rr[4];
                ldm4t(rr, v_base + (unsigned)sw16(kc2 * 16 + (lane & 15), dnp * 2 + (lane >> 4)) * 2);
                mma16816h(oacc[dnp * 2 + 0], pa, rr[0], rr[1]);
                mma16816h(oacc[dnp * 2 + 1], pa, rr[2], rr[3]);
            }
        }
        __syncthreads();
        if (t + 2 < ntiles)
            attn_load_tile(KsA[t & 1], VsA[t & 1], kbase + (size_t)(t + 2) * 64 * HD,
                           vbase + (size_t)(t + 2) * 64 * HD, tid);
        cp_commit();
    }

    // --- write normalized output: out[(b*SEQL + qrow)*HID + h*128 + d] ---
    float inv0 = 1.f / l0, inv1 = 1.f / l1;
    size_t o0 = ((size_t)b * SEQL + qr0) * HID + h * HD;
    size_t o1 = o0 + 8 * HID;
#pragma unroll
    for (int dnt = 0; dnt < 16; dnt++) {
        int d = dnt * 8 + c2;
        float2 v0 = make_float2(oacc[dnt][0] * inv0, oacc[dnt][1] * inv0);
        float2 v1 = make_float2(oacc[dnt][2] * inv1, oacc[dnt][3] * inv1);
        *(float2*)(out + o0 + d) = v0;
        *(float2*)(out + o1 + d) = v1;
    }
}

// ------------------------- elementwise -------------------------
__global__ void add_kernel(const float* __restrict__ a, const float* __restrict__ b,
                           float* __restrict__ c, int n) {
    int i = blockIdx.x * blockDim.x + threadIdx.x;
    if (i < n) c[i] = a[i] + b[i];
}

// ------------------------- host orchestration -------------------------
extern "C" void kernel_launch(void* const* d_in, const int* in_sizes, int n_in,
                              void* d_out, int out_size) {
    const float* x     = (const float*)d_in[0];
    const int*   amask = (const int*)d_in[1];
    const float* wq = (const float*)d_in[2];   const float* aq_a = (const float*)d_in[3];
    const float* wk = (const float*)d_in[4];   const float* ak_a = (const float*)d_in[5];
    const float* wv = (const float*)d_in[6];   const float* av_a = (const float*)d_in[7];
    const float* wo = (const float*)d_in[8];   const float* ao_a = (const float*)d_in[9];
    const float* wg = (const float*)d_in[10];  const float* ag_a = (const float*)d_in[11];
    const float* wu = (const float*)d_in[12];  const float* au_a = (const float*)d_in[13];
    const float* wd = (const float*)d_in[14];  const float* ad_a = (const float*)d_in[15];
    const float* n1 = (const float*)d_in[16];
    const float* n2 = (const float*)d_in[17];
    float* out = (float*)d_out;

    __nv_bfloat16 *p_wq, *p_wk, *p_wv, *p_wo, *p_wg, *p_wu, *p_wd, *p_aq;
    __half *p_qh, *p_kh, *p_vh;
    float *p_sq, *p_sk, *p_sv, *p_so, *p_sg, *p_su, *p_sd;
    float *p_as, *p_qkv, *p_attno, *p_x1, *p_gate, *p_up, *p_down;
    cudaGetSymbolAddress((void**)&p_wq, g_wq);
    cudaGetSymbolAddress((void**)&p_wk, g_wk);
    cudaGetSymbolAddress((void**)&p_wv, g_wv);
    cudaGetSymbolAddress((void**)&p_wo, g_wo);
    cudaGetSymbolAddress((void**)&p_wg, g_wg);
    cudaGetSymbolAddress((void**)&p_wu, g_wu);
    cudaGetSymbolAddress((void**)&p_wd, g_wd);
    cudaGetSymbolAddress((void**)&p_sq, g_sq);
    cudaGetSymbolAddress((void**)&p_sk, g_sk);
    cudaGetSymbolAddress((void**)&p_sv, g_sv);
    cudaGetSymbolAddress((void**)&p_so, g_so);
    cudaGetSymbolAddress((void**)&p_sg, g_sg);
    cudaGetSymbolAddress((void**)&p_su, g_su);
    cudaGetSymbolAddress((void**)&p_sd, g_sd);
    cudaGetSymbolAddress((void**)&p_aq, g_aq);
    cudaGetSymbolAddress((void**)&p_as, g_as);
    cudaGetSymbolAddress((void**)&p_qkv, g_qkv);
    cudaGetSymbolAddress((void**)&p_qh, g_qh);
    cudaGetSymbolAddress((void**)&p_kh, g_kh);
    cudaGetSymbolAddress((void**)&p_vh, g_vh);
    cudaGetSymbolAddress((void**)&p_attno, g_attno);
    cudaGetSymbolAddress((void**)&p_x1, g_x1);
    cudaGetSymbolAddress((void**)&p_gate, g_gate);
    cudaGetSymbolAddress((void**)&p_up, g_up);
    cudaGetSymbolAddress((void**)&p_down, g_down);

    const int smem_bytes = 2 * (BM * BK + BN * BK) * 2;   // 65536
    cudaFuncSetAttribute(gemm_bf16_kernel, cudaFuncAttributeMaxDynamicSharedMemorySize, smem_bytes);
    const int attn_smem = 40960 * 2;                      // 81920
    cudaFuncSetAttribute(attn_mma_kernel, cudaFuncAttributeMaxDynamicSharedMemorySize, attn_smem);

    // 1) quantize all weights (bf16)
    quant_w_kernel<<<HID, 256>>>(wq, aq_a, p_wq, p_sq, HID);
    quant_w_kernel<<<HID, 256>>>(wk, ak_a, p_wk, p_sk, HID);
    quant_w_kernel<<<HID, 256>>>(wv, av_a, p_wv, p_sv, HID);
    quant_w_kernel<<<HID, 256>>>(wo, ao_a, p_wo, p_so, HID);
    quant_w_kernel<<<MLPD, 256>>>(wg, ag_a, p_wg, p_sg, HID);
    quant_w_kernel<<<MLPD, 256>>>(wu, au_a, p_wu, p_su, HID);
    quant_w_kernel<<<HID, 256>>>(wd, ad_a, p_wd, p_sd, MLPD);

    // 2) rmsnorm + quantize input
    rms_quant_kernel<<<NTOK, 256>>>(x, n1, p_aq, p_as);

    // 3) q,k,v projections
    dim3 g16(HID / BN, NTOK / BM);
    gemm_bf16_kernel<<<g16, 256, smem_bytes>>>(p_aq, p_wq, p_sq, p_as, p_qkv, HID, HID);
    gemm_bf16_kernel<<<g16, 256, smem_bytes>>>(p_aq, p_wk, p_sk, p_as, p_qkv + (size_t)NTOK * HID, HID, HID);
    gemm_bf16_kernel<<<g16, 256, smem_bytes>>>(p_aq, p_wv, p_sv, p_as, p_qkv + 2 * (size_t)NTOK * HID, HID, HID);

    // 4) rope + transpose + fp16 convert
    rope_half_kernel<<<(NTOK * NH * 64 + 255) / 256, 256>>>(
        p_qkv, p_qkv + (size_t)NTOK * HID, p_qkv + 2 * (size_t)NTOK * HID, p_qh, p_kh, p_vh);

    // 5) mma flash attention
    attn_mma_kernel<<<(SEQL / 64) * 32, 128, attn_smem>>>(p_qh, p_kh, p_vh, amask, p_attno);

    // 6) output projection
    act_quant_kernel<<<NTOK, 256>>>(p_attno, p_aq, p_as, HID);
    gemm_bf16_kernel<<<g16, 256, smem_bytes>>>(p_aq, p_wo, p_so, p_as, p_down, HID, HID);

    // 7) residual + rmsnorm + quant (fused)
    add_rms_quant_kernel<<<NTOK, 256>>>(x, p_down, n2, p_x1, p_aq, p_as);

    // 8) MLP
    dim3 g64(MLPD / BN, NTOK / BM);
    gemm_bf16_kernel<<<g64, 256, smem_bytes>>>(p_aq, p_wg, p_sg, p_as, p_gate, HID, MLPD);
    gemm_bf16_kernel<<<g64, 256, smem_bytes>>>(p_aq, p_wu, p_su, p_as, p_up, HID, MLPD);
    silu_quant_kernel<<<NTOK, 512>>>(p_gate, p_up, p_aq, p_as);
    gemm_bf16_kernel<<<g16, 256, smem_bytes>>>(p_aq, p_wd, p_sd, p_as, p_down, MLPD, HID);

    // 9) final residual into d_out
    add_kernel<<<NTOK * HID / 256, 256>>>(p_x1, p_down, out, NTOK * HID);
    (void)in_sizes; (void)n_in; (void)out_size;
}